// round 9
// baseline (speedup 1.0000x reference)
#include <cuda_runtime.h>
#include <cuda_fp16.h>

#define BB    8
#define SS    4096
#define HH    2048
#define DHH   64
#define KSEL  256

typedef unsigned long long ull;

// scratch (no cudaMalloc allowed)
__device__ float d_logits[BB * SS];
__device__ int   d_sel[BB * KSEL];

__device__ __forceinline__ void fma2(ull& c, ull a, ull b) {
    asm("fma.rn.f32x2 %0, %1, %2, %0;" : "+l"(c) : "l"(a), "l"(b));
}
__device__ __forceinline__ ull mk64(unsigned lo, unsigned hi) {
    ull r; asm("mov.b64 %0, {%1, %2};" : "=l"(r) : "r"(lo), "r"(hi)); return r;
}
__device__ __forceinline__ ull dup64(float a) {
    ull r; asm("mov.b64 %0, {%1, %1};" : "=l"(r) : "f"(a)); return r;
}
// fp32 rounded through fp16 (reference does .astype(float16); harness compares fp32)
__device__ __forceinline__ float h16(float v) {
    return __half2float(__float2half_rn(v));
}

// ============================================================================
// Kernel 1: fused logits GEMM. 16 tok x 8 col per thread (128 fp32 acc as
// 64 packed f32x2) so the per-warp-kk budget is LDS 24 wf + global ~7.5 wf
// vs 64 FFMA2 (32 SM-cyc) -> balanced at the fma floor.
// BM=256, BK=8, 128 threads, double-buffered single-sync pipeline,
// + fp16-rounded fp32 copy of hidden_states into out.
// ============================================================================
constexpr int BM = 256, BK = 8, NCHUNK = HH / BK;
constexpr int APAD = BK + 4;   // 12-float stride: float4-aligned, bank-spread

__global__ __launch_bounds__(128, 2)
void k_gemm(const float* __restrict__ hs, const float* __restrict__ w1,
            const float* __restrict__ b1, const float* __restrict__ w2,
            const float* __restrict__ b2, float* __restrict__ out)
{
    __shared__ float a_s[2][BM][APAD];   // 24.6KB, non-duplicated
    __shared__ float b_s[2][BK][DHH];    // 4KB

    const int tid  = threadIdx.x;
    const int tx   = tid & 7;
    const int ty   = tid >> 3;               // 0..15
    const int tok0 = blockIdx.x * BM;

    // A staging: 256 rows x 8 floats = 512 float4; flat = i*128 + tid (i=0..3)
    // row = 64*i + (tid>>1), kq = (tid&1)*4
    const int arow = tid >> 1;                // 0..63 (+64i)
    const int akq  = (tid & 1) * 4;           // 0 or 4
    // B staging: 8 rows x 64 floats = 128 float4; one per thread
    const int br   = tid >> 4;                // 0..7
    const int bc   = (tid & 15) * 4;

    const float* hsA = hs  + (size_t)(tok0 + arow) * HH + akq;
    float*       oA  = out + (size_t)(tok0 + arow) * HH + akq;

    ull acc[16][4];
#pragma unroll
    for (int t = 0; t < 16; t++)
#pragma unroll
        for (int i = 0; i < 4; i++) acc[t][i] = 0ull;

    float4 va[4], vb;
    // ---- prologue: chunk 0 ----
#pragma unroll
    for (int i = 0; i < 4; i++)
        va[i] = *reinterpret_cast<const float4*>(hsA + (size_t)(64 * i) * HH);
    vb = *reinterpret_cast<const float4*>(w1 + (size_t)br * DHH + bc);
#pragma unroll
    for (int i = 0; i < 4; i++) {
        *reinterpret_cast<float4*>(&a_s[0][64 * i + arow][akq]) = va[i];
        *reinterpret_cast<float4*>(oA + (size_t)(64 * i) * HH) =
            make_float4(h16(va[i].x), h16(va[i].y), h16(va[i].z), h16(va[i].w));
    }
    *reinterpret_cast<float4*>(&b_s[0][br][bc]) = vb;
    __syncthreads();

    for (int c = 0; c < NCHUNK; c++) {
        const int buf = c & 1;

        // prefetch chunk c+1 into registers (overlaps compute below)
        if (c + 1 < NCHUNK) {
#pragma unroll
            for (int i = 0; i < 4; i++)
                va[i] = *reinterpret_cast<const float4*>(
                    hsA + (size_t)(64 * i) * HH + (size_t)(c + 1) * BK);
            vb = *reinterpret_cast<const float4*>(
                     w1 + (size_t)((c + 1) * BK + br) * DHH + bc);
        }

        // compute chunk c from smem[buf]
#pragma unroll
        for (int kk = 0; kk < BK; kk++) {
            const uint4 u0 = *reinterpret_cast<const uint4*>(&b_s[buf][kk][tx * 8]);
            const uint4 u1 = *reinterpret_cast<const uint4*>(&b_s[buf][kk][tx * 8 + 4]);
            const ull bv0 = mk64(u0.x, u0.y), bv1 = mk64(u0.z, u0.w);
            const ull bv2 = mk64(u1.x, u1.y), bv3 = mk64(u1.z, u1.w);
#pragma unroll
            for (int t = 0; t < 16; t++) {
                const ull av = dup64(a_s[buf][ty + 16 * t][kk]);
                fma2(acc[t][0], av, bv0);
                fma2(acc[t][1], av, bv1);
                fma2(acc[t][2], av, bv2);
                fma2(acc[t][3], av, bv3);
            }
        }

        // stage chunk c+1 into the other buffer; emit output copy
        if (c + 1 < NCHUNK) {
            const int nb = buf ^ 1;
#pragma unroll
            for (int i = 0; i < 4; i++) {
                *reinterpret_cast<float4*>(&a_s[nb][64 * i + arow][akq]) = va[i];
                *reinterpret_cast<float4*>(
                    oA + (size_t)(64 * i) * HH + (size_t)(c + 1) * BK) =
                    make_float4(h16(va[i].x), h16(va[i].y), h16(va[i].z), h16(va[i].w));
            }
            *reinterpret_cast<float4*>(&b_s[nb][br][bc]) = vb;
            __syncthreads();
        }
    }

    // epilogue: +b1, relu, dot w2, reduce over 8 tx lanes
    const float4 b1a = *reinterpret_cast<const float4*>(b1 + tx * 8);
    const float4 b1b = *reinterpret_cast<const float4*>(b1 + tx * 8 + 4);
    const float4 w2a = *reinterpret_cast<const float4*>(w2 + tx * 8);
    const float4 w2b = *reinterpret_cast<const float4*>(w2 + tx * 8 + 4);
    const float b2v = b2[0];
    const float b1v[8] = {b1a.x, b1a.y, b1a.z, b1a.w, b1b.x, b1b.y, b1b.z, b1b.w};
    const float w2v[8] = {w2a.x, w2a.y, w2a.z, w2a.w, w2b.x, w2b.y, w2b.z, w2b.w};

#pragma unroll
    for (int t = 0; t < 16; t++) {
        float p = 0.f;
#pragma unroll
        for (int i = 0; i < 4; i++) {
            float lo = __uint_as_float((unsigned)(acc[t][i] & 0xffffffffull));
            float hi = __uint_as_float((unsigned)(acc[t][i] >> 32));
            p += fmaxf(lo + b1v[2 * i],     0.f) * w2v[2 * i]
               + fmaxf(hi + b1v[2 * i + 1], 0.f) * w2v[2 * i + 1];
        }
        p += __shfl_down_sync(0xffffffffu, p, 4, 8);
        p += __shfl_down_sync(0xffffffffu, p, 2, 8);
        p += __shfl_down_sync(0xffffffffu, p, 1, 8);
        if (tx == 0) d_logits[tok0 + ty + 16 * t] = p + b2v;
    }
}

// ============================================================================
// Kernel 2: per-batch gumbel top-k (full bitonic sort, matches jax.lax.top_k
// descending order + stable lowest-index tiebreak) + logsumexp + log_prob.
// ============================================================================
__global__ __launch_bounds__(512)
void k_topk(const float* __restrict__ noise, float* __restrict__ out,
            int write_extras)
{
    const int b   = blockIdx.x;
    const int tid = threadIdx.x;
    __shared__ ull   keys[SS];
    __shared__ float red[512];

    const float* lg = d_logits + b * SS;
    const float* nu = noise    + b * SS;

    float m = -3.4e38f;
    for (int i = tid; i < SS; i += 512) {
        float l = lg[i];
        float s = l - logf(-logf(nu[i]));          // logit + gumbel
        unsigned u = __float_as_uint(s);
        u = (u & 0x80000000u) ? ~u : (u | 0x80000000u);
        keys[i] = ((ull)u << 32) | (unsigned)(~(unsigned)i);
        m = fmaxf(m, l);
    }
    red[tid] = m; __syncthreads();
    for (int s2 = 256; s2 > 0; s2 >>= 1) {
        if (tid < s2) red[tid] = fmaxf(red[tid], red[tid + s2]);
        __syncthreads();
    }
    m = red[0]; __syncthreads();
    float sum = 0.f;
    for (int i = tid; i < SS; i += 512) sum += expf(lg[i] - m);
    red[tid] = sum; __syncthreads();
    for (int s2 = 256; s2 > 0; s2 >>= 1) {
        if (tid < s2) red[tid] += red[tid + s2];
        __syncthreads();
    }
    const float lse = m + logf(red[0]);
    __syncthreads();

    for (int size = 2; size <= SS; size <<= 1) {
        for (int stride = size >> 1; stride > 0; stride >>= 1) {
            for (int t = tid; t < SS / 2; t += 512) {
                int i = 2 * t - (t & (stride - 1));
                int j = i + stride;
                bool desc = ((i & size) == 0);
                ull a = keys[i], c = keys[j];
                bool sw = desc ? (a < c) : (a > c);
                if (sw) { keys[i] = c; keys[j] = a; }
            }
            __syncthreads();
        }
    }

    float lp = 0.f;
    for (int kk = tid; kk < KSEL; kk += 512) {
        int idx = (int)(~(unsigned)(keys[kk] & 0xffffffffull));
        d_sel[b * KSEL + kk] = idx;
        lp += lg[idx] - lse;
        if (write_extras) {
            out[(size_t)BB * SS * HH + b * KSEL + kk] = (float)idx;           // indices
            out[(size_t)BB * SS * HH + BB * KSEL + b * KSEL + kk] = 1.0f;     // types
        }
    }
    red[tid] = lp; __syncthreads();
    for (int s2 = 256; s2 > 0; s2 >>= 1) {
        if (tid < s2) red[tid] += red[tid + s2];
        __syncthreads();
    }
    if (tid == 0 && write_extras)
        out[(size_t)BB * SS * HH + 2 * BB * KSEL + b] = red[0] / (float)KSEL; // log_prob
}

// ============================================================================
// Kernel 3: zero selected rows (perturb value = TYPE_VALUES[1]*SCALE = 0.0)
// ============================================================================
__global__ __launch_bounds__(256)
void k_zero(float* __restrict__ out)
{
    const int b   = blockIdx.y;
    const int row = d_sel[b * KSEL + blockIdx.x];
    float4* p = reinterpret_cast<float4*>(out + ((size_t)b * SS + row) * HH);
    const float4 z = make_float4(0.f, 0.f, 0.f, 0.f);
    p[threadIdx.x]       = z;
    p[threadIdx.x + 256] = z;
}

// ============================================================================
extern "C" void kernel_launch(void* const* d_in, const int* in_sizes, int n_in,
                              void* d_out, int out_size)
{
    const float* hs = (const float*)d_in[0];   // (8,4096,2048) fp32
    const float* nu = (const float*)d_in[1];   // (8,4096)      fp32
    const float* w1 = (const float*)d_in[2];   // (2048,64)
    const float* b1 = (const float*)d_in[3];   // (64,)
    const float* w2 = (const float*)d_in[4];   // (64,1)
    const float* b2 = (const float*)d_in[5];   // (1,)
    float* out = (float*)d_out;

    const long long need = (long long)BB * SS * HH + 2LL * BB * KSEL + BB;
    const int write_extras = ((long long)out_size >= need) ? 1 : 0;

    k_gemm<<<(BB * SS) / BM, 128>>>(hs, w1, b1, w2, b2, out);
    k_topk<<<BB, 512>>>(nu, out, write_extras);
    k_zero<<<dim3(KSEL, BB), 256>>>(out);
    (void)in_sizes; (void)n_in;
}

// round 10
// speedup vs baseline: 1.9474x; 1.9474x over previous
#include <cuda_runtime.h>
#include <cuda_fp16.h>
#include <cuda_bf16.h>

#define BB    8
#define SS    4096
#define HH    2048
#define DHH   64
#define KSEL  256

typedef unsigned long long ull;
typedef unsigned int u32;

// scratch (no cudaMalloc allowed)
__device__ float d_logits[BB * SS];
__device__ int   d_sel[BB * KSEL];

// fp32 rounded through fp16 (reference does .astype(float16); harness compares fp32)
__device__ __forceinline__ float h16(float v) {
    return __half2float(__float2half_rn(v));
}
// pack two fp32 -> bf16x2 (lo half = b, hi half = a)
__device__ __forceinline__ u32 bf2(float a, float b) {
    u32 r; asm("cvt.rn.bf16x2.f32 %0, %1, %2;" : "=r"(r) : "f"(a), "f"(b)); return r;
}
__device__ __forceinline__ unsigned smem_u32(const void* p) {
    unsigned r;
    asm("{ .reg .u64 t; cvta.to.shared.u64 t, %1; cvt.u32.u64 %0, t; }"
        : "=r"(r) : "l"(p));
    return r;
}
__device__ __forceinline__ void sts64(u32 addr, u32 a, u32 b) {
    asm volatile("st.shared.v2.u32 [%0], {%1, %2};" :: "r"(addr), "r"(a), "r"(b));
}
__device__ __forceinline__ void ldsm4(u32* r, u32 addr) {
    asm volatile("ldmatrix.sync.aligned.m8n8.x4.shared.b16 {%0,%1,%2,%3}, [%4];"
                 : "=r"(r[0]), "=r"(r[1]), "=r"(r[2]), "=r"(r[3]) : "r"(addr));
}
__device__ __forceinline__ void ldsm4t(u32* r, u32 addr) {
    asm volatile("ldmatrix.sync.aligned.m8n8.x4.trans.shared.b16 {%0,%1,%2,%3}, [%4];"
                 : "=r"(r[0]), "=r"(r[1]), "=r"(r[2]), "=r"(r[3]) : "r"(addr));
}
__device__ __forceinline__ void mma_bf16(float* d, const u32* a, u32 b0, u32 b1) {
    asm volatile(
        "mma.sync.aligned.m16n8k16.row.col.f32.bf16.bf16.f32 "
        "{%0,%1,%2,%3}, {%4,%5,%6,%7}, {%8,%9}, {%0,%1,%2,%3};"
        : "+f"(d[0]), "+f"(d[1]), "+f"(d[2]), "+f"(d[3])
        : "r"(a[0]), "r"(a[1]), "r"(a[2]), "r"(a[3]), "r"(b0), "r"(b1));
}
__device__ __forceinline__ int swz(int b) { return b ^ ((b >> 3) & 0x70); }

// ============================================================================
// Kernel 1: logits GEMM on tensor cores (bf16 hi/lo split, 3 MMA terms),
// double-buffered single-sync pipeline, + fp16-rounded fp32 copy of hs to out.
// Block: 256 thr (8 warps). BM=128 tokens (warp w -> rows 16w..16w+15, all 64
// cols). K-chunk 32 (2 k-tiles of 16). grid = 256.
// smem: A 2x16KB (row=token, 128B = 32 hi bf16 | 32 lo bf16, swizzled)
//       B 2x8KB  (hi 4KB [k][n] bf16 + lo 4KB, swizzled)
// ============================================================================
constexpr int BKC = 32, NCH = HH / BKC;   // 64 chunks

__global__ __launch_bounds__(256, 2)
void k_gemm(const float* __restrict__ hs, const float* __restrict__ w1,
            const float* __restrict__ b1, const float* __restrict__ w2,
            const float* __restrict__ b2, float* __restrict__ out)
{
    __shared__ __align__(1024) unsigned char sm[49152];
    const u32 smA = smem_u32(sm);          // 2 x 16384
    const u32 smB = smA + 32768;           // 2 x 8192 (hi 4096 | lo 4096)

    const int tid  = threadIdx.x;
    const int warp = tid >> 5;
    const int lane = tid & 31;
    const int tok0 = blockIdx.x * 128;

    // ---- staging maps ----
    // X: 128 rows x 32 k fp32; thread does 4 float4: row = 32i + (tid>>3)
    const int rx = tid >> 3;
    const int kq = (tid & 7) * 4;
    u32 stsXhi[4], stsXlo[4];
    const float* pX[4];
    float*       pO[4];
#pragma unroll
    for (int i = 0; i < 4; i++) {
        const int row = i * 32 + rx;
        const int bo  = row * 128 + kq * 2;
        stsXhi[i] = smA + swz(bo);
        stsXlo[i] = smA + swz(bo + 64);
        pX[i] = hs  + (size_t)(tok0 + row) * HH + kq;
        pO[i] = out + (size_t)(tok0 + row) * HH + kq;
    }
    // W: 32 rows x 64 n fp32; thread does 2 float4: k = 16i + (tid>>4)
    const int kw = tid >> 4;
    const int n4 = (tid & 15) * 4;
    u32 stsW[2];
    const float* pW[2];
#pragma unroll
    for (int i = 0; i < 2; i++) {
        const int k  = i * 16 + kw;
        stsW[i] = smB + swz(k * 128 + n4 * 2);
        pW[i]   = w1 + (size_t)k * DHH + n4;
    }

    // ---- ldmatrix lane addresses ----
    const int lr = lane & 7, g1 = (lane >> 3) & 1, g2 = lane >> 4;
    const int rA = warp * 16 + g1 * 8 + lr;
    u32 aHi[2], aLo[2], rbB[2], xmB[2];
#pragma unroll
    for (int kt = 0; kt < 2; kt++) {
        aHi[kt] = smA + swz(rA * 128 + kt * 32 + g2 * 16);
        aLo[kt] = smA + swz(rA * 128 + kt * 32 + g2 * 16 + 64);
        const int rb = (kt * 16 + g1 * 8 + lr) * 128;
        rbB[kt] = smB + rb;
        xmB[kt] = (rb >> 3) & 0x70;
    }
    const int cpg = g2 * 16;

    float acc[8][4];
#pragma unroll
    for (int n = 0; n < 8; n++)
#pragma unroll
        for (int i = 0; i < 4; i++) acc[n][i] = 0.f;

    float4 va[4], vw[2];

#define LOADC(c)                                                              \
    do {                                                                      \
        _Pragma("unroll")                                                     \
        for (int i = 0; i < 4; i++)                                           \
            va[i] = *reinterpret_cast<const float4*>(pX[i] + (size_t)(c) * BKC); \
        _Pragma("unroll")                                                     \
        for (int i = 0; i < 2; i++)                                           \
            vw[i] = *reinterpret_cast<const float4*>(pW[i] + (size_t)(c) * BKC * DHH); \
    } while (0)

#define STAGE(bb, c)                                                          \
    do {                                                                      \
        _Pragma("unroll")                                                     \
        for (int i = 0; i < 4; i++) {                                         \
            u32 h01 = bf2(va[i].y, va[i].x), h23 = bf2(va[i].w, va[i].z);     \
            float f0 = __uint_as_float(h01 << 16);                            \
            float f1 = __uint_as_float(h01 & 0xffff0000u);                    \
            float f2 = __uint_as_float(h23 << 16);                            \
            float f3 = __uint_as_float(h23 & 0xffff0000u);                    \
            u32 l01 = bf2(va[i].y - f1, va[i].x - f0);                        \
            u32 l23 = bf2(va[i].w - f3, va[i].z - f2);                        \
            sts64(stsXhi[i] + (bb) * 16384, h01, h23);                        \
            sts64(stsXlo[i] + (bb) * 16384, l01, l23);                        \
            *reinterpret_cast<float4*>(pO[i] + (size_t)(c) * BKC) =           \
                make_float4(h16(va[i].x), h16(va[i].y),                       \
                            h16(va[i].z), h16(va[i].w));                      \
        }                                                                     \
        _Pragma("unroll")                                                     \
        for (int i = 0; i < 2; i++) {                                         \
            u32 h01 = bf2(vw[i].y, vw[i].x), h23 = bf2(vw[i].w, vw[i].z);     \
            float f0 = __uint_as_float(h01 << 16);                            \
            float f1 = __uint_as_float(h01 & 0xffff0000u);                    \
            float f2 = __uint_as_float(h23 << 16);                            \
            float f3 = __uint_as_float(h23 & 0xffff0000u);                    \
            u32 l01 = bf2(vw[i].y - f1, vw[i].x - f0);                        \
            u32 l23 = bf2(vw[i].w - f3, vw[i].z - f2);                        \
            sts64(stsW[i] + (bb) * 8192, h01, h23);                           \
            sts64(stsW[i] + (bb) * 8192 + 4096, l01, l23);                    \
        }                                                                     \
    } while (0)

    // ---- prologue ----
    LOADC(0);
    STAGE(0, 0);
    __syncthreads();

    for (int c = 0; c < NCH; c++) {
        const int bb = c & 1;
        if (c + 1 < NCH) LOADC(c + 1);

        // compute chunk c
#pragma unroll
        for (int kt = 0; kt < 2; kt++) {
            u32 ah[4], al[4];
            ldsm4(ah, aHi[kt] + bb * 16384);
            ldsm4(al, aLo[kt] + bb * 16384);
#pragma unroll
            for (int ntp = 0; ntp < 4; ntp++) {
                u32 bh[4], bl[4];
                const u32 ba = rbB[kt] + bb * 8192 + ((ntp * 32 + cpg) ^ xmB[kt]);
                ldsm4t(bh, ba);
                ldsm4t(bl, ba + 4096);
                mma_bf16(acc[2 * ntp],     ah, bh[0], bh[1]);
                mma_bf16(acc[2 * ntp + 1], ah, bh[2], bh[3]);
                mma_bf16(acc[2 * ntp],     ah, bl[0], bl[1]);
                mma_bf16(acc[2 * ntp + 1], ah, bl[2], bl[3]);
                mma_bf16(acc[2 * ntp],     al, bh[0], bh[1]);
                mma_bf16(acc[2 * ntp + 1], al, bh[2], bh[3]);
            }
        }

        if (c + 1 < NCH) {
            STAGE(bb ^ 1, c + 1);
            __syncthreads();
        }
    }

    // ---- epilogue: relu(C+b1)·w2 + b2 -> d_logits ----
    const int m2 = (lane & 3) * 2;
    float p0 = 0.f, p1 = 0.f;
#pragma unroll
    for (int nt = 0; nt < 8; nt++) {
        const int n = nt * 8 + m2;
        const float b10 = b1[n], b11 = b1[n + 1];
        const float w20 = w2[n], w21 = w2[n + 1];
        p0 += fmaxf(acc[nt][0] + b10, 0.f) * w20 + fmaxf(acc[nt][1] + b11, 0.f) * w21;
        p1 += fmaxf(acc[nt][2] + b10, 0.f) * w20 + fmaxf(acc[nt][3] + b11, 0.f) * w21;
    }
    p0 += __shfl_xor_sync(0xffffffffu, p0, 1);
    p0 += __shfl_xor_sync(0xffffffffu, p0, 2);
    p1 += __shfl_xor_sync(0xffffffffu, p1, 1);
    p1 += __shfl_xor_sync(0xffffffffu, p1, 2);
    if ((lane & 3) == 0) {
        const int row = tok0 + warp * 16 + (lane >> 2);
        const float b2v = b2[0];
        d_logits[row]     = p0 + b2v;
        d_logits[row + 8] = p1 + b2v;
    }
#undef LOADC
#undef STAGE
}

// ============================================================================
// Kernel 2: per-batch gumbel top-k (full bitonic sort, matches jax.lax.top_k
// descending order + stable lowest-index tiebreak) + logsumexp + log_prob.
// ============================================================================
__global__ __launch_bounds__(512)
void k_topk(const float* __restrict__ noise, float* __restrict__ out,
            int write_extras)
{
    const int b   = blockIdx.x;
    const int tid = threadIdx.x;
    __shared__ ull   keys[SS];
    __shared__ float red[512];

    const float* lg = d_logits + b * SS;
    const float* nu = noise    + b * SS;

    float m = -3.4e38f;
    for (int i = tid; i < SS; i += 512) {
        float l = lg[i];
        float s = l - logf(-logf(nu[i]));          // logit + gumbel
        unsigned u = __float_as_uint(s);
        u = (u & 0x80000000u) ? ~u : (u | 0x80000000u);
        keys[i] = ((ull)u << 32) | (unsigned)(~(unsigned)i);
        m = fmaxf(m, l);
    }
    red[tid] = m; __syncthreads();
    for (int s2 = 256; s2 > 0; s2 >>= 1) {
        if (tid < s2) red[tid] = fmaxf(red[tid], red[tid + s2]);
        __syncthreads();
    }
    m = red[0]; __syncthreads();
    float sum = 0.f;
    for (int i = tid; i < SS; i += 512) sum += expf(lg[i] - m);
    red[tid] = sum; __syncthreads();
    for (int s2 = 256; s2 > 0; s2 >>= 1) {
        if (tid < s2) red[tid] += red[tid + s2];
        __syncthreads();
    }
    const float lse = m + logf(red[0]);
    __syncthreads();

    for (int size = 2; size <= SS; size <<= 1) {
        for (int stride = size >> 1; stride > 0; stride >>= 1) {
            for (int t = tid; t < SS / 2; t += 512) {
                int i = 2 * t - (t & (stride - 1));
                int j = i + stride;
                bool desc = ((i & size) == 0);
                ull a = keys[i], c = keys[j];
                bool sw = desc ? (a < c) : (a > c);
                if (sw) { keys[i] = c; keys[j] = a; }
            }
            __syncthreads();
        }
    }

    float lp = 0.f;
    for (int kk = tid; kk < KSEL; kk += 512) {
        int idx = (int)(~(unsigned)(keys[kk] & 0xffffffffull));
        d_sel[b * KSEL + kk] = idx;
        lp += lg[idx] - lse;
        if (write_extras) {
            out[(size_t)BB * SS * HH + b * KSEL + kk] = (float)idx;           // indices
            out[(size_t)BB * SS * HH + BB * KSEL + b * KSEL + kk] = 1.0f;     // types
        }
    }
    red[tid] = lp; __syncthreads();
    for (int s2 = 256; s2 > 0; s2 >>= 1) {
        if (tid < s2) red[tid] += red[tid + s2];
        __syncthreads();
    }
    if (tid == 0 && write_extras)
        out[(size_t)BB * SS * HH + 2 * BB * KSEL + b] = red[0] / (float)KSEL; // log_prob
}

// ============================================================================
// Kernel 3: zero selected rows (perturb value = TYPE_VALUES[1]*SCALE = 0.0)
// ============================================================================
__global__ __launch_bounds__(256)
void k_zero(float* __restrict__ out)
{
    const int b   = blockIdx.y;
    const int row = d_sel[b * KSEL + blockIdx.x];
    float4* p = reinterpret_cast<float4*>(out + ((size_t)b * SS + row) * HH);
    const float4 z = make_float4(0.f, 0.f, 0.f, 0.f);
    p[threadIdx.x]       = z;
    p[threadIdx.x + 256] = z;
}

// ============================================================================
extern "C" void kernel_launch(void* const* d_in, const int* in_sizes, int n_in,
                              void* d_out, int out_size)
{
    const float* hs = (const float*)d_in[0];   // (8,4096,2048) fp32
    const float* nu = (const float*)d_in[1];   // (8,4096)      fp32
    const float* w1 = (const float*)d_in[2];   // (2048,64)
    const float* b1 = (const float*)d_in[3];   // (64,)
    const float* w2 = (const float*)d_in[4];   // (64,1)
    const float* b2 = (const float*)d_in[5];   // (1,)
    float* out = (float*)d_out;

    const long long need = (long long)BB * SS * HH + 2LL * BB * KSEL + BB;
    const int write_extras = ((long long)out_size >= need) ? 1 : 0;

    k_gemm<<<(BB * SS) / 128, 256>>>(hs, w1, b1, w2, b2, out);
    k_topk<<<BB, 512>>>(nu, out, write_extras);
    k_zero<<<dim3(KSEL, BB), 256>>>(out);
    (void)in_sizes; (void)n_in;
}

// round 11
// speedup vs baseline: 2.2238x; 1.1419x over previous
#include <cuda_runtime.h>
#include <cuda_fp16.h>
#include <cuda_bf16.h>

#define BB    8
#define SS    4096
#define HH    2048
#define DHH   64
#define KSEL  256

typedef unsigned long long ull;
typedef unsigned int u32;

// scratch (no cudaMalloc allowed)
__device__ float d_logits[BB * SS];
__device__ int   d_sel[BB * KSEL];

// fp32 rounded through fp16 (reference does .astype(float16); harness compares fp32)
__device__ __forceinline__ float h16(float v) {
    return __half2float(__float2half_rn(v));
}
// pack two fp32 -> bf16x2 (lo half = b, hi half = a)
__device__ __forceinline__ u32 bf2(float a, float b) {
    u32 r; asm("cvt.rn.bf16x2.f32 %0, %1, %2;" : "=r"(r) : "f"(a), "f"(b)); return r;
}
__device__ __forceinline__ unsigned smem_u32(const void* p) {
    unsigned r;
    asm("{ .reg .u64 t; cvta.to.shared.u64 t, %1; cvt.u32.u64 %0, t; }"
        : "=r"(r) : "l"(p));
    return r;
}
__device__ __forceinline__ void sts64(u32 addr, u32 a, u32 b) {
    asm volatile("st.shared.v2.u32 [%0], {%1, %2};" :: "r"(addr), "r"(a), "r"(b));
}
__device__ __forceinline__ void ldsm4(u32* r, u32 addr) {
    asm volatile("ldmatrix.sync.aligned.m8n8.x4.shared.b16 {%0,%1,%2,%3}, [%4];"
                 : "=r"(r[0]), "=r"(r[1]), "=r"(r[2]), "=r"(r[3]) : "r"(addr));
}
__device__ __forceinline__ void ldsm4t(u32* r, u32 addr) {
    asm volatile("ldmatrix.sync.aligned.m8n8.x4.trans.shared.b16 {%0,%1,%2,%3}, [%4];"
                 : "=r"(r[0]), "=r"(r[1]), "=r"(r[2]), "=r"(r[3]) : "r"(addr));
}
__device__ __forceinline__ void mma_bf16(float* d, const u32* a, u32 b0, u32 b1) {
    asm volatile(
        "mma.sync.aligned.m16n8k16.row.col.f32.bf16.bf16.f32 "
        "{%0,%1,%2,%3}, {%4,%5,%6,%7}, {%8,%9}, {%0,%1,%2,%3};"
        : "+f"(d[0]), "+f"(d[1]), "+f"(d[2]), "+f"(d[3])
        : "r"(a[0]), "r"(a[1]), "r"(a[2]), "r"(a[3]), "r"(b0), "r"(b1));
}
__device__ __forceinline__ int swz(int b) { return b ^ ((b >> 3) & 0x70); }

// ============================================================================
// Kernel 1: logits GEMM on tensor cores (bf16 hi/lo split, 3 MMA terms),
// 3-stage smem pipeline with prefetch distance 2 (hides DRAM latency),
// + fp16-rounded fp32 copy of hs to out.
// Block: 256 thr (8 warps). BM=128 tokens, K-chunk 32. grid = 256.
// smem (dynamic 72KB): A 3x16KB (row 128B = 32 hi bf16 | 32 lo bf16, swizzled)
//                      B 3x8KB  (hi 4KB [k][n] + lo 4KB, swizzled)
// ============================================================================
constexpr int BKC = 32, NCH = HH / BKC;   // 64 chunks
constexpr int A_STG = 16384, B_STG = 8192;
constexpr int SMEM_BYTES = 3 * (A_STG + B_STG);   // 73728

__global__ __launch_bounds__(256, 2)
void k_gemm(const float* __restrict__ hs, const float* __restrict__ w1,
            const float* __restrict__ b1, const float* __restrict__ w2,
            const float* __restrict__ b2, float* __restrict__ out)
{
    extern __shared__ __align__(1024) unsigned char sm[];
    const u32 smA = smem_u32(sm);              // 3 x 16384
    const u32 smB = smA + 3 * A_STG;           // 3 x 8192 (hi 4096 | lo 4096)

    const int tid  = threadIdx.x;
    const int warp = tid >> 5;
    const int lane = tid & 31;
    const int tok0 = blockIdx.x * 128;

    // ---- staging maps ----
    // X: 128 rows x 32 k fp32; thread does 4 float4: row = 32i + (tid>>3)
    const int rx = tid >> 3;
    const int kq = (tid & 7) * 4;
    u32 stsXhi[4], stsXlo[4];
    const float* pX[4];
    float*       pO[4];
#pragma unroll
    for (int i = 0; i < 4; i++) {
        const int row = i * 32 + rx;
        const int bo  = row * 128 + kq * 2;
        stsXhi[i] = smA + swz(bo);
        stsXlo[i] = smA + swz(bo + 64);
        pX[i] = hs  + (size_t)(tok0 + row) * HH + kq;
        pO[i] = out + (size_t)(tok0 + row) * HH + kq;
    }
    // W: 32 rows x 64 n fp32; thread does 2 float4: k = 16i + (tid>>4)
    const int kw = tid >> 4;
    const int n4 = (tid & 15) * 4;
    u32 stsW[2];
    const float* pW[2];
#pragma unroll
    for (int i = 0; i < 2; i++) {
        const int k  = i * 16 + kw;
        stsW[i] = smB + swz(k * 128 + n4 * 2);
        pW[i]   = w1 + (size_t)k * DHH + n4;
    }

    // ---- ldmatrix lane addresses ----
    const int lr = lane & 7, g1 = (lane >> 3) & 1, g2 = lane >> 4;
    const int rA = warp * 16 + g1 * 8 + lr;
    u32 aHi[2], aLo[2], rbB[2], xmB[2];
#pragma unroll
    for (int kt = 0; kt < 2; kt++) {
        aHi[kt] = smA + swz(rA * 128 + kt * 32 + g2 * 16);
        aLo[kt] = smA + swz(rA * 128 + kt * 32 + g2 * 16 + 64);
        const int rb = (kt * 16 + g1 * 8 + lr) * 128;
        rbB[kt] = smB + rb;
        xmB[kt] = (rb >> 3) & 0x70;
    }
    const int cpg = g2 * 16;

    float acc[8][4];
#pragma unroll
    for (int n = 0; n < 8; n++)
#pragma unroll
        for (int i = 0; i < 4; i++) acc[n][i] = 0.f;

    float4 va[4], vw[2];

#define LOADC(c)                                                              \
    do {                                                                      \
        _Pragma("unroll")                                                     \
        for (int i = 0; i < 4; i++)                                           \
            va[i] = *reinterpret_cast<const float4*>(pX[i] + (size_t)(c) * BKC); \
        _Pragma("unroll")                                                     \
        for (int i = 0; i < 2; i++)                                           \
            vw[i] = *reinterpret_cast<const float4*>(pW[i] + (size_t)(c) * BKC * DHH); \
    } while (0)

#define STAGE(sb, c)                                                          \
    do {                                                                      \
        _Pragma("unroll")                                                     \
        for (int i = 0; i < 4; i++) {                                         \
            u32 h01 = bf2(va[i].y, va[i].x), h23 = bf2(va[i].w, va[i].z);     \
            float f0 = __uint_as_float(h01 << 16);                            \
            float f1 = __uint_as_float(h01 & 0xffff0000u);                    \
            float f2 = __uint_as_float(h23 << 16);                            \
            float f3 = __uint_as_float(h23 & 0xffff0000u);                    \
            u32 l01 = bf2(va[i].y - f1, va[i].x - f0);                        \
            u32 l23 = bf2(va[i].w - f3, va[i].z - f2);                        \
            sts64(stsXhi[i] + (sb) * A_STG, h01, h23);                        \
            sts64(stsXlo[i] + (sb) * A_STG, l01, l23);                        \
            *reinterpret_cast<float4*>(pO[i] + (size_t)(c) * BKC) =           \
                make_float4(h16(va[i].x), h16(va[i].y),                       \
                            h16(va[i].z), h16(va[i].w));                      \
        }                                                                     \
        _Pragma("unroll")                                                     \
        for (int i = 0; i < 2; i++) {                                         \
            u32 h01 = bf2(vw[i].y, vw[i].x), h23 = bf2(vw[i].w, vw[i].z);     \
            float f0 = __uint_as_float(h01 << 16);                            \
            float f1 = __uint_as_float(h01 & 0xffff0000u);                    \
            float f2 = __uint_as_float(h23 << 16);                            \
            float f3 = __uint_as_float(h23 & 0xffff0000u);                    \
            u32 l01 = bf2(vw[i].y - f1, vw[i].x - f0);                        \
            u32 l23 = bf2(vw[i].w - f3, vw[i].z - f2);                        \
            sts64(stsW[i] + (sb) * B_STG, h01, h23);                          \
            sts64(stsW[i] + (sb) * B_STG + 4096, l01, l23);                   \
        }                                                                     \
    } while (0)

    // ---- prologue: stage chunks 0,1; regs hold chunk 2 ----
    LOADC(0); STAGE(0, 0);
    LOADC(1); STAGE(1, 1);
    LOADC(2);
    __syncthreads();

    int cmod = 0, smod = 2;
    for (int c = 0; c < NCH; c++) {
        // compute chunk c from buffer cmod
#pragma unroll
        for (int kt = 0; kt < 2; kt++) {
            u32 ah[4], al[4];
            ldsm4(ah, aHi[kt] + cmod * A_STG);
            ldsm4(al, aLo[kt] + cmod * A_STG);
#pragma unroll
            for (int ntp = 0; ntp < 4; ntp++) {
                u32 bh[4], bl[4];
                const u32 ba = rbB[kt] + cmod * B_STG + ((ntp * 32 + cpg) ^ xmB[kt]);
                ldsm4t(bh, ba);
                ldsm4t(bl, ba + 4096);
                mma_bf16(acc[2 * ntp],     ah, bh[0], bh[1]);
                mma_bf16(acc[2 * ntp + 1], ah, bh[2], bh[3]);
                mma_bf16(acc[2 * ntp],     ah, bl[0], bl[1]);
                mma_bf16(acc[2 * ntp + 1], ah, bl[2], bl[3]);
                mma_bf16(acc[2 * ntp],     al, bh[0], bh[1]);
                mma_bf16(acc[2 * ntp + 1], al, bh[2], bh[3]);
            }
        }

        // stage chunk c+2 (regs) into buffer smod; refill regs with chunk c+3
        if (c + 2 < NCH) {
            STAGE(smod, c + 2);
            if (c + 3 < NCH) LOADC(c + 3);
        }
        if (++cmod == 3) cmod = 0;
        if (++smod == 3) smod = 0;
        __syncthreads();
    }

    // ---- epilogue: relu(C+b1)·w2 + b2 -> d_logits ----
    const int m2 = (lane & 3) * 2;
    float p0 = 0.f, p1 = 0.f;
#pragma unroll
    for (int nt = 0; nt < 8; nt++) {
        const int n = nt * 8 + m2;
        const float b10 = b1[n], b11 = b1[n + 1];
        const float w20 = w2[n], w21 = w2[n + 1];
        p0 += fmaxf(acc[nt][0] + b10, 0.f) * w20 + fmaxf(acc[nt][1] + b11, 0.f) * w21;
        p1 += fmaxf(acc[nt][2] + b10, 0.f) * w20 + fmaxf(acc[nt][3] + b11, 0.f) * w21;
    }
    p0 += __shfl_xor_sync(0xffffffffu, p0, 1);
    p0 += __shfl_xor_sync(0xffffffffu, p0, 2);
    p1 += __shfl_xor_sync(0xffffffffu, p1, 1);
    p1 += __shfl_xor_sync(0xffffffffu, p1, 2);
    if ((lane & 3) == 0) {
        const int row = tok0 + warp * 16 + (lane >> 2);
        const float b2v = b2[0];
        d_logits[row]     = p0 + b2v;
        d_logits[row + 8] = p1 + b2v;
    }
#undef LOADC
#undef STAGE
}

// ============================================================================
// Kernel 2: per-batch gumbel top-k (full bitonic sort, matches jax.lax.top_k
// descending order + stable lowest-index tiebreak) + logsumexp + log_prob.
// ============================================================================
__global__ __launch_bounds__(512)
void k_topk(const float* __restrict__ noise, float* __restrict__ out,
            int write_extras)
{
    const int b   = blockIdx.x;
    const int tid = threadIdx.x;
    __shared__ ull   keys[SS];
    __shared__ float red[512];

    const float* lg = d_logits + b * SS;
    const float* nu = noise    + b * SS;

    float m = -3.4e38f;
    for (int i = tid; i < SS; i += 512) {
        float l = lg[i];
        float s = l - logf(-logf(nu[i]));          // logit + gumbel
        unsigned u = __float_as_uint(s);
        u = (u & 0x80000000u) ? ~u : (u | 0x80000000u);
        keys[i] = ((ull)u << 32) | (unsigned)(~(unsigned)i);
        m = fmaxf(m, l);
    }
    red[tid] = m; __syncthreads();
    for (int s2 = 256; s2 > 0; s2 >>= 1) {
        if (tid < s2) red[tid] = fmaxf(red[tid], red[tid + s2]);
        __syncthreads();
    }
    m = red[0]; __syncthreads();
    float sum = 0.f;
    for (int i = tid; i < SS; i += 512) sum += expf(lg[i] - m);
    red[tid] = sum; __syncthreads();
    for (int s2 = 256; s2 > 0; s2 >>= 1) {
        if (tid < s2) red[tid] += red[tid + s2];
        __syncthreads();
    }
    const float lse = m + logf(red[0]);
    __syncthreads();

    for (int size = 2; size <= SS; size <<= 1) {
        for (int stride = size >> 1; stride > 0; stride >>= 1) {
            for (int t = tid; t < SS / 2; t += 512) {
                int i = 2 * t - (t & (stride - 1));
                int j = i + stride;
                bool desc = ((i & size) == 0);
                ull a = keys[i], c = keys[j];
                bool sw = desc ? (a < c) : (a > c);
                if (sw) { keys[i] = c; keys[j] = a; }
            }
            __syncthreads();
        }
    }

    float lp = 0.f;
    for (int kk = tid; kk < KSEL; kk += 512) {
        int idx = (int)(~(unsigned)(keys[kk] & 0xffffffffull));
        d_sel[b * KSEL + kk] = idx;
        lp += lg[idx] - lse;
        if (write_extras) {
            out[(size_t)BB * SS * HH + b * KSEL + kk] = (float)idx;           // indices
            out[(size_t)BB * SS * HH + BB * KSEL + b * KSEL + kk] = 1.0f;     // types
        }
    }
    red[tid] = lp; __syncthreads();
    for (int s2 = 256; s2 > 0; s2 >>= 1) {
        if (tid < s2) red[tid] += red[tid + s2];
        __syncthreads();
    }
    if (tid == 0 && write_extras)
        out[(size_t)BB * SS * HH + 2 * BB * KSEL + b] = red[0] / (float)KSEL; // log_prob
}

// ============================================================================
// Kernel 3: zero selected rows (perturb value = TYPE_VALUES[1]*SCALE = 0.0)
// ============================================================================
__global__ __launch_bounds__(256)
void k_zero(float* __restrict__ out)
{
    const int b   = blockIdx.y;
    const int row = d_sel[b * KSEL + blockIdx.x];
    float4* p = reinterpret_cast<float4*>(out + ((size_t)b * SS + row) * HH);
    const float4 z = make_float4(0.f, 0.f, 0.f, 0.f);
    p[threadIdx.x]       = z;
    p[threadIdx.x + 256] = z;
}

// ============================================================================
extern "C" void kernel_launch(void* const* d_in, const int* in_sizes, int n_in,
                              void* d_out, int out_size)
{
    const float* hs = (const float*)d_in[0];   // (8,4096,2048) fp32
    const float* nu = (const float*)d_in[1];   // (8,4096)      fp32
    const float* w1 = (const float*)d_in[2];   // (2048,64)
    const float* b1 = (const float*)d_in[3];   // (64,)
    const float* w2 = (const float*)d_in[4];   // (64,1)
    const float* b2 = (const float*)d_in[5];   // (1,)
    float* out = (float*)d_out;

    const long long need = (long long)BB * SS * HH + 2LL * BB * KSEL + BB;
    const int write_extras = ((long long)out_size >= need) ? 1 : 0;

    cudaFuncSetAttribute(k_gemm, cudaFuncAttributeMaxDynamicSharedMemorySize,
                         SMEM_BYTES);
    k_gemm<<<(BB * SS) / 128, 256, SMEM_BYTES>>>(hs, w1, b1, w2, b2, out);
    k_topk<<<BB, 512>>>(nu, out, write_extras);
    k_zero<<<dim3(KSEL, BB), 256>>>(out);
    (void)in_sizes; (void)n_in;
}

// round 12
// speedup vs baseline: 2.3438x; 1.0539x over previous
#include <cuda_runtime.h>
#include <cuda_fp16.h>
#include <cuda_bf16.h>

#define BB    8
#define SS    4096
#define HH    2048
#define DHH   64
#define KSEL  256

typedef unsigned long long ull;
typedef unsigned int u32;

// scratch (no cudaMalloc allowed)
__device__ float d_logits[BB * SS];
__device__ int   d_sel[BB * KSEL];

// fp32 rounded through fp16 (reference does .astype(float16); harness compares fp32)
__device__ __forceinline__ float h16(float v) {
    return __half2float(__float2half_rn(v));
}
// pack two fp32 -> bf16x2 (lo half = b, hi half = a)
__device__ __forceinline__ u32 bf2(float a, float b) {
    u32 r; asm("cvt.rn.bf16x2.f32 %0, %1, %2;" : "=r"(r) : "f"(a), "f"(b)); return r;
}
__device__ __forceinline__ unsigned smem_u32(const void* p) {
    unsigned r;
    asm("{ .reg .u64 t; cvta.to.shared.u64 t, %1; cvt.u32.u64 %0, t; }"
        : "=r"(r) : "l"(p));
    return r;
}
__device__ __forceinline__ void sts64(u32 addr, u32 a, u32 b) {
    asm volatile("st.shared.v2.u32 [%0], {%1, %2};" :: "r"(addr), "r"(a), "r"(b));
}
__device__ __forceinline__ void ldsm4(u32* r, u32 addr) {
    asm volatile("ldmatrix.sync.aligned.m8n8.x4.shared.b16 {%0,%1,%2,%3}, [%4];"
                 : "=r"(r[0]), "=r"(r[1]), "=r"(r[2]), "=r"(r[3]) : "r"(addr));
}
__device__ __forceinline__ void ldsm4t(u32* r, u32 addr) {
    asm volatile("ldmatrix.sync.aligned.m8n8.x4.trans.shared.b16 {%0,%1,%2,%3}, [%4];"
                 : "=r"(r[0]), "=r"(r[1]), "=r"(r[2]), "=r"(r[3]) : "r"(addr));
}
__device__ __forceinline__ void mma_bf16(float* d, const u32* a, u32 b0, u32 b1) {
    asm volatile(
        "mma.sync.aligned.m16n8k16.row.col.f32.bf16.bf16.f32 "
        "{%0,%1,%2,%3}, {%4,%5,%6,%7}, {%8,%9}, {%0,%1,%2,%3};"
        : "+f"(d[0]), "+f"(d[1]), "+f"(d[2]), "+f"(d[3])
        : "r"(a[0]), "r"(a[1]), "r"(a[2]), "r"(a[3]), "r"(b0), "r"(b1));
}
__device__ __forceinline__ int swz(int b) { return b ^ ((b >> 3) & 0x70); }

// ============================================================================
// Kernel 1: logits GEMM on tensor cores (bf16 hi/lo split, 3 MMA terms),
// 4-stage smem pipeline with prefetch distance 3 (hides DRAM latency),
// + fp16-rounded fp32 copy of hs to out.
// Block: 256 thr (8 warps). BM=128 tokens, K-chunk 32. grid = 256.
// smem (dynamic 96KB): A 4x16KB (row 128B = 32 hi bf16 | 32 lo bf16, swizzled)
//                      B 4x8KB  (hi 4KB [k][n] + lo 4KB, swizzled)
// ============================================================================
constexpr int BKC = 32, NCH = HH / BKC;   // 64 chunks
constexpr int A_STG = 16384, B_STG = 8192;
constexpr int NSTG = 4;
constexpr int SMEM_BYTES = NSTG * (A_STG + B_STG);   // 98304

__global__ __launch_bounds__(256, 2)
void k_gemm(const float* __restrict__ hs, const float* __restrict__ w1,
            const float* __restrict__ b1, const float* __restrict__ w2,
            const float* __restrict__ b2, float* __restrict__ out)
{
    extern __shared__ __align__(1024) unsigned char sm[];
    const u32 smA = smem_u32(sm);                 // 4 x 16384
    const u32 smB = smA + NSTG * A_STG;           // 4 x 8192 (hi 4096 | lo 4096)

    const int tid  = threadIdx.x;
    const int warp = tid >> 5;
    const int lane = tid & 31;
    const int tok0 = blockIdx.x * 128;

    // ---- staging maps ----
    // X: 128 rows x 32 k fp32; thread does 4 float4: row = 32i + (tid>>3)
    const int rx = tid >> 3;
    const int kq = (tid & 7) * 4;
    u32 stsXhi[4], stsXlo[4];
    const float* pX[4];
    float*       pO[4];
#pragma unroll
    for (int i = 0; i < 4; i++) {
        const int row = i * 32 + rx;
        const int bo  = row * 128 + kq * 2;
        stsXhi[i] = smA + swz(bo);
        stsXlo[i] = smA + swz(bo + 64);
        pX[i] = hs  + (size_t)(tok0 + row) * HH + kq;
        pO[i] = out + (size_t)(tok0 + row) * HH + kq;
    }
    // W: 32 rows x 64 n fp32; thread does 2 float4: k = 16i + (tid>>4)
    const int kw = tid >> 4;
    const int n4 = (tid & 15) * 4;
    u32 stsW[2];
    const float* pW[2];
#pragma unroll
    for (int i = 0; i < 2; i++) {
        const int k  = i * 16 + kw;
        stsW[i] = smB + swz(k * 128 + n4 * 2);
        pW[i]   = w1 + (size_t)k * DHH + n4;
    }

    // ---- ldmatrix lane addresses ----
    const int lr = lane & 7, g1 = (lane >> 3) & 1, g2 = lane >> 4;
    const int rA = warp * 16 + g1 * 8 + lr;
    u32 aHi[2], aLo[2], rbB[2], xmB[2];
#pragma unroll
    for (int kt = 0; kt < 2; kt++) {
        aHi[kt] = smA + swz(rA * 128 + kt * 32 + g2 * 16);
        aLo[kt] = smA + swz(rA * 128 + kt * 32 + g2 * 16 + 64);
        const int rb = (kt * 16 + g1 * 8 + lr) * 128;
        rbB[kt] = smB + rb;
        xmB[kt] = (rb >> 3) & 0x70;
    }
    const int cpg = g2 * 16;

    float acc[8][4];
#pragma unroll
    for (int n = 0; n < 8; n++)
#pragma unroll
        for (int i = 0; i < 4; i++) acc[n][i] = 0.f;

    float4 va[4], vw[2];

#define LOADC(c)                                                              \
    do {                                                                      \
        _Pragma("unroll")                                                     \
        for (int i = 0; i < 4; i++)                                           \
            va[i] = *reinterpret_cast<const float4*>(pX[i] + (size_t)(c) * BKC); \
        _Pragma("unroll")                                                     \
        for (int i = 0; i < 2; i++)                                           \
            vw[i] = *reinterpret_cast<const float4*>(pW[i] + (size_t)(c) * BKC * DHH); \
    } while (0)

#define STAGE(sb, c)                                                          \
    do {                                                                      \
        _Pragma("unroll")                                                     \
        for (int i = 0; i < 4; i++) {                                         \
            u32 h01 = bf2(va[i].y, va[i].x), h23 = bf2(va[i].w, va[i].z);     \
            float f0 = __uint_as_float(h01 << 16);                            \
            float f1 = __uint_as_float(h01 & 0xffff0000u);                    \
            float f2 = __uint_as_float(h23 << 16);                            \
            float f3 = __uint_as_float(h23 & 0xffff0000u);                    \
            u32 l01 = bf2(va[i].y - f1, va[i].x - f0);                        \
            u32 l23 = bf2(va[i].w - f3, va[i].z - f2);                        \
            sts64(stsXhi[i] + (sb) * A_STG, h01, h23);                        \
            sts64(stsXlo[i] + (sb) * A_STG, l01, l23);                        \
            *reinterpret_cast<float4*>(pO[i] + (size_t)(c) * BKC) =           \
                make_float4(h16(va[i].x), h16(va[i].y),                       \
                            h16(va[i].z), h16(va[i].w));                      \
        }                                                                     \
        _Pragma("unroll")                                                     \
        for (int i = 0; i < 2; i++) {                                         \
            u32 h01 = bf2(vw[i].y, vw[i].x), h23 = bf2(vw[i].w, vw[i].z);     \
            float f0 = __uint_as_float(h01 << 16);                            \
            float f1 = __uint_as_float(h01 & 0xffff0000u);                    \
            float f2 = __uint_as_float(h23 << 16);                            \
            float f3 = __uint_as_float(h23 & 0xffff0000u);                    \
            u32 l01 = bf2(vw[i].y - f1, vw[i].x - f0);                        \
            u32 l23 = bf2(vw[i].w - f3, vw[i].z - f2);                        \
            sts64(stsW[i] + (sb) * B_STG, h01, h23);                          \
            sts64(stsW[i] + (sb) * B_STG + 4096, l01, l23);                   \
        }                                                                     \
    } while (0)

    // ---- prologue: stage chunks 0,1,2; regs hold chunk 3 ----
    LOADC(0); STAGE(0, 0);
    LOADC(1); STAGE(1, 1);
    LOADC(2); STAGE(2, 2);
    LOADC(3);
    __syncthreads();

    int cmod = 0, smod = 3;
    for (int c = 0; c < NCH; c++) {
        // compute chunk c from buffer cmod
#pragma unroll
        for (int kt = 0; kt < 2; kt++) {
            u32 ah[4], al[4];
            ldsm4(ah, aHi[kt] + cmod * A_STG);
            ldsm4(al, aLo[kt] + cmod * A_STG);
#pragma unroll
            for (int ntp = 0; ntp < 4; ntp++) {
                u32 bh[4], bl[4];
                const u32 ba = rbB[kt] + cmod * B_STG + ((ntp * 32 + cpg) ^ xmB[kt]);
                ldsm4t(bh, ba);
                ldsm4t(bl, ba + 4096);
                mma_bf16(acc[2 * ntp],     ah, bh[0], bh[1]);
                mma_bf16(acc[2 * ntp + 1], ah, bh[2], bh[3]);
                mma_bf16(acc[2 * ntp],     ah, bl[0], bl[1]);
                mma_bf16(acc[2 * ntp + 1], ah, bl[2], bl[3]);
                mma_bf16(acc[2 * ntp],     al, bh[0], bh[1]);
                mma_bf16(acc[2 * ntp + 1], al, bh[2], bh[3]);
            }
        }

        // stage chunk c+3 (regs) into buffer smod; refill regs with chunk c+4
        if (c + 3 < NCH) {
            STAGE(smod, c + 3);
            if (c + 4 < NCH) LOADC(c + 4);
        }
        cmod = (cmod + 1) & 3;
        smod = (smod + 1) & 3;
        __syncthreads();
    }

    // ---- epilogue: relu(C+b1)·w2 + b2 -> d_logits ----
    const int m2 = (lane & 3) * 2;
    float p0 = 0.f, p1 = 0.f;
#pragma unroll
    for (int nt = 0; nt < 8; nt++) {
        const int n = nt * 8 + m2;
        const float b10 = b1[n], b11 = b1[n + 1];
        const float w20 = w2[n], w21 = w2[n + 1];
        p0 += fmaxf(acc[nt][0] + b10, 0.f) * w20 + fmaxf(acc[nt][1] + b11, 0.f) * w21;
        p1 += fmaxf(acc[nt][2] + b10, 0.f) * w20 + fmaxf(acc[nt][3] + b11, 0.f) * w21;
    }
    p0 += __shfl_xor_sync(0xffffffffu, p0, 1);
    p0 += __shfl_xor_sync(0xffffffffu, p0, 2);
    p1 += __shfl_xor_sync(0xffffffffu, p1, 1);
    p1 += __shfl_xor_sync(0xffffffffu, p1, 2);
    if ((lane & 3) == 0) {
        const int row = tok0 + warp * 16 + (lane >> 2);
        const float b2v = b2[0];
        d_logits[row]     = p0 + b2v;
        d_logits[row + 8] = p1 + b2v;
    }
#undef LOADC
#undef STAGE
}

// ============================================================================
// Kernel 2: per-batch gumbel top-k via bitonic SELECTION (not full sort):
// sort 16 chunks of 256 (alternating dir), then 4 rounds of
// {pairwise half-cleaner keep-max, re-sort surviving 256-chunks}.
// Keys unique (index embedded) -> identical result & order to jax.lax.top_k.
// Also computes logsumexp + mean log-prob of selected.
// ============================================================================
__global__ __launch_bounds__(512)
void k_topk(const float* __restrict__ noise, float* __restrict__ out,
            int write_extras)
{
    const int b   = blockIdx.x;
    const int tid = threadIdx.x;
    __shared__ ull   keys[SS];
    __shared__ float red[512];

    const float* lg = d_logits + b * SS;
    const float* nu = noise    + b * SS;

    float m = -3.4e38f;
    for (int i = tid; i < SS; i += 512) {
        float l = lg[i];
        float s = l - logf(-logf(nu[i]));          // logit + gumbel
        unsigned u = __float_as_uint(s);
        u = (u & 0x80000000u) ? ~u : (u | 0x80000000u);
        keys[i] = ((ull)u << 32) | (unsigned)(~(unsigned)i);
        m = fmaxf(m, l);
    }
    red[tid] = m; __syncthreads();
    for (int s2 = 256; s2 > 0; s2 >>= 1) {
        if (tid < s2) red[tid] = fmaxf(red[tid], red[tid + s2]);
        __syncthreads();
    }
    m = red[0]; __syncthreads();
    float sum = 0.f;
    for (int i = tid; i < SS; i += 512) sum += expf(lg[i] - m);
    red[tid] = sum; __syncthreads();
    for (int s2 = 256; s2 > 0; s2 >>= 1) {
        if (tid < s2) red[tid] += red[tid + s2];
        __syncthreads();
    }
    const float lse = m + logf(red[0]);
    __syncthreads();

    // phase 1: truncated bitonic network -> each 256-chunk sorted,
    // even chunks descending, odd chunks ascending
    for (int size = 2; size <= 256; size <<= 1) {
        for (int stride = size >> 1; stride > 0; stride >>= 1) {
            for (int t = tid; t < SS / 2; t += 512) {
                int i = 2 * t - (t & (stride - 1));
                int j = i + stride;
                bool desc = ((i & size) == 0);
                ull a = keys[i], c = keys[j];
                bool sw = desc ? (a < c) : (a > c);
                if (sw) { keys[i] = c; keys[j] = a; }
            }
            __syncthreads();
        }
    }

    // phase 2: selection rounds. Adjacent (desc,asc) chunk pairs are bitonic;
    // half-cleaner keeps the 256 largest of each 512 (result bitonic), then
    // re-sort surviving chunks (alternating dir; final round all-desc).
    for (int n = SS; n > 256; n >>= 1) {
        const int half = n >> 1;
        ull v[4];
        int cnt = 0;
        for (int p = tid; p < half; p += 512) {
            const int cix = p >> 8, i2 = p & 255;
            const ull a = keys[cix * 512 + i2];
            const ull c = keys[cix * 512 + i2 + 256];
            v[cnt++] = (a > c) ? a : c;
        }
        __syncthreads();
        cnt = 0;
        for (int p = tid; p < half; p += 512) keys[p] = v[cnt++];
        __syncthreads();

        const bool fin = (half == 256);
        for (int stride = 128; stride > 0; stride >>= 1) {
            for (int t = tid; t < (half >> 1); t += 512) {
                int i = 2 * t - (t & (stride - 1));
                int j = i + stride;
                bool desc = fin || (((i >> 8) & 1) == 0);
                ull a = keys[i], c = keys[j];
                bool sw = desc ? (a < c) : (a > c);
                if (sw) { keys[i] = c; keys[j] = a; }
            }
            __syncthreads();
        }
    }

    float lp = 0.f;
    for (int kk = tid; kk < KSEL; kk += 512) {
        int idx = (int)(~(unsigned)(keys[kk] & 0xffffffffull));
        d_sel[b * KSEL + kk] = idx;
        lp += lg[idx] - lse;
        if (write_extras) {
            out[(size_t)BB * SS * HH + b * KSEL + kk] = (float)idx;           // indices
            out[(size_t)BB * SS * HH + BB * KSEL + b * KSEL + kk] = 1.0f;     // types
        }
    }
    red[tid] = lp; __syncthreads();
    for (int s2 = 256; s2 > 0; s2 >>= 1) {
        if (tid < s2) red[tid] += red[tid + s2];
        __syncthreads();
    }
    if (tid == 0 && write_extras)
        out[(size_t)BB * SS * HH + 2 * BB * KSEL + b] = red[0] / (float)KSEL; // log_prob
}

// ============================================================================
// Kernel 3: zero selected rows (perturb value = TYPE_VALUES[1]*SCALE = 0.0)
// ============================================================================
__global__ __launch_bounds__(256)
void k_zero(float* __restrict__ out)
{
    const int b   = blockIdx.y;
    const int row = d_sel[b * KSEL + blockIdx.x];
    float4* p = reinterpret_cast<float4*>(out + ((size_t)b * SS + row) * HH);
    const float4 z = make_float4(0.f, 0.f, 0.f, 0.f);
    p[threadIdx.x]       = z;
    p[threadIdx.x + 256] = z;
}

// ============================================================================
extern "C" void kernel_launch(void* const* d_in, const int* in_sizes, int n_in,
                              void* d_out, int out_size)
{
    const float* hs = (const float*)d_in[0];   // (8,4096,2048) fp32
    const float* nu = (const float*)d_in[1];   // (8,4096)      fp32
    const float* w1 = (const float*)d_in[2];   // (2048,64)
    const float* b1 = (const float*)d_in[3];   // (64,)
    const float* w2 = (const float*)d_in[4];   // (64,1)
    const float* b2 = (const float*)d_in[5];   // (1,)
    float* out = (float*)d_out;

    const long long need = (long long)BB * SS * HH + 2LL * BB * KSEL + BB;
    const int write_extras = ((long long)out_size >= need) ? 1 : 0;

    cudaFuncSetAttribute(k_gemm, cudaFuncAttributeMaxDynamicSharedMemorySize,
                         SMEM_BYTES);
    k_gemm<<<(BB * SS) / 128, 256, SMEM_BYTES>>>(hs, w1, b1, w2, b2, out);
    k_topk<<<BB, 512>>>(nu, out, write_extras);
    k_zero<<<dim3(KSEL, BB), 256>>>(out);
    (void)in_sizes; (void)n_in;
}